// round 8
// baseline (speedup 1.0000x reference)
#include <cuda_runtime.h>
#include <cuda_fp16.h>
#include <cstdint>

#define NN 50000
#define NE 1600000
#define DIN 256
#define DH 128
#define DO 40

#define SCAN_BLK 512
#define SCAN_NB ((NN + SCAN_BLK - 1) / SCAN_BLK)   // 98

// -------- scratch (static device globals; no allocation allowed) --------
static __device__ __align__(16) __half g_h1h[(size_t)NN * DH];   // x@W1 (fp16, gather source)
static __device__ __align__(16) __half g_a1h[(size_t)NN * DH];   // relu(agg1+b1) (fp16)
static __device__ __align__(16) __half g_h2h[(size_t)NN * DO];   // layer2 pre-agg (fp16)
static __device__ int      g_deg[NN];
static __device__ float    g_dinv[NN];
static __device__ int      g_off[NN];
static __device__ int      g_pos[NN];
static __device__ int      g_inc[SCAN_NB * SCAN_BLK];
static __device__ int      g_bsum[SCAN_NB];
static __device__ unsigned g_edge[NE];   // packed: (src << 16) | fp16(coef)
static __device__ int      g_is64;

// -------- edge index accessors (dtype-agnostic) --------
__device__ __forceinline__ int e_src(const void* ei, int t) {
    return g_is64 ? (int)((const long long*)ei)[t] : ((const int*)ei)[t];
}
__device__ __forceinline__ int e_dst(const void* ei, int t) {
    return g_is64 ? (int)((const long long*)ei)[NE + t] : ((const int*)ei)[NE + t];
}

// -------- init: zero degree counters + detect edge dtype --------
__global__ void k_init(const int* __restrict__ ei32) {
    if (blockIdx.x == gridDim.x - 1) {
        int t = threadIdx.x;
        if (t == 0) g_is64 = 1;
        __syncthreads();
        int any = 0;
        for (int i = t; i < 2048; i += blockDim.x) any |= ei32[2 * i + 1];
        if (any) g_is64 = 0;
        return;
    }
    int t = blockIdx.x * blockDim.x + threadIdx.x;
    if (t < NN) g_deg[t] = 0;
}

// -------- degree histogram: 4 edges/thread on int32 path --------
__global__ void k_deg(const void* __restrict__ ei) {
    int t = blockIdx.x * blockDim.x + threadIdx.x;
    if (!g_is64) {
        if (t < NE / 4) {
            int4 d4 = ((const int4*)((const int*)ei + NE))[t];
            if ((unsigned)d4.x < NN) atomicAdd(&g_deg[d4.x], 1);
            if ((unsigned)d4.y < NN) atomicAdd(&g_deg[d4.y], 1);
            if ((unsigned)d4.z < NN) atomicAdd(&g_deg[d4.z], 1);
            if ((unsigned)d4.w < NN) atomicAdd(&g_deg[d4.w], 1);
        }
    } else {
        for (int e = t * 4; e < t * 4 + 4 && e < NE; e++) {
            int d = (int)((const long long*)ei)[NE + e];
            if ((unsigned)d < NN) atomicAdd(&g_deg[d], 1);
        }
    }
}

// -------- scan level 1: per-block inclusive scan --------
__global__ void k_scan_block() {
    __shared__ int sh[SCAN_BLK];
    int t = threadIdx.x;
    int i = blockIdx.x * SCAN_BLK + t;
    int v = (i < NN) ? g_deg[i] : 0;
    sh[t] = v;
    __syncthreads();
#pragma unroll
    for (int o = 1; o < SCAN_BLK; o <<= 1) {
        int x = (t >= o) ? sh[t - o] : 0;
        __syncthreads();
        sh[t] += x;
        __syncthreads();
    }
    g_inc[i] = sh[t];
    if (t == SCAN_BLK - 1) g_bsum[blockIdx.x] = sh[t];
}

// -------- scan fix (+ in-block top scan) + dinv --------
__global__ void k_scan_fix() {
    __shared__ int sb[SCAN_NB];
    if (threadIdx.x == 0) {
        int run = 0;
        for (int i = 0; i < SCAN_NB; i++) { sb[i] = run; run += g_bsum[i]; }
    }
    __syncthreads();
    int t = blockIdx.x * blockDim.x + threadIdx.x;
    if (t < NN) {
        int dg = g_deg[t];
        int off = g_inc[t] - dg + sb[t / SCAN_BLK];  // exclusive
        g_off[t] = off;
        g_pos[t] = off;
        g_dinv[t] = rsqrtf((float)(dg + 1));
    }
}

// -------- CSR fill: packed (src:16 | coef:fp16), 4 edges/thread on int32 path --------
__global__ void k_scatter(const void* __restrict__ ei) {
    int t = blockIdx.x * blockDim.x + threadIdx.x;
    if (!g_is64) {
        if (t < NE / 4) {
            int4 s4 = ((const int4*)ei)[t];
            int4 d4 = ((const int4*)((const int*)ei + NE))[t];
            int ss[4] = {s4.x, s4.y, s4.z, s4.w};
            int dd[4] = {d4.x, d4.y, d4.z, d4.w};
#pragma unroll
            for (int q = 0; q < 4; q++) {
                int s = ss[q], d = dd[q];
                if ((unsigned)s < NN && (unsigned)d < NN) {
                    int slot = atomicAdd(&g_pos[d], 1);
                    unsigned hb = __half_as_ushort(__float2half_rn(g_dinv[s] * g_dinv[d]));
                    g_edge[slot] = ((unsigned)s << 16) | hb;
                }
            }
        }
    } else {
        for (int e = t * 4; e < t * 4 + 4 && e < NE; e++) {
            int s = (int)((const long long*)ei)[e];
            int d = (int)((const long long*)ei)[NE + e];
            if ((unsigned)s < NN && (unsigned)d < NN) {
                int slot = atomicAdd(&g_pos[d], 1);
                unsigned hb = __half_as_ushort(__float2half_rn(g_dinv[s] * g_dinv[d]));
                g_edge[slot] = ((unsigned)s << 16) | hb;
            }
        }
    }
}

__device__ __forceinline__ void unpack_edge(unsigned e, int& s, float& c) {
    s = (int)(e >> 16);
    c = __half2float(__ushort_as_half((unsigned short)(e & 0xffffu)));
}

// -------- async copy helpers --------
__device__ __forceinline__ void cp_async16(void* smem, const void* gmem, bool pred) {
    uint32_t sa = (uint32_t)__cvta_generic_to_shared(smem);
    int sz = pred ? 16 : 0;
    asm volatile("cp.async.cg.shared.global [%0], [%1], 16, %2;" :: "r"(sa), "l"(gmem), "r"(sz));
}
__device__ __forceinline__ void cp_commit() { asm volatile("cp.async.commit_group;"); }
template <int N>
__device__ __forceinline__ void cp_wait() { asm volatile("cp.async.wait_group %0;" :: "n"(N)); }

__device__ __forceinline__ void mma_tf32(float& d0, float& d1, float& d2, float& d3,
                                         uint32_t a0, uint32_t a1, uint32_t a2, uint32_t a3,
                                         uint32_t b0, uint32_t b1) {
    asm volatile(
        "mma.sync.aligned.m16n8k8.row.col.f32.tf32.tf32.f32 "
        "{%0,%1,%2,%3}, {%4,%5,%6,%7}, {%8,%9}, {%0,%1,%2,%3};"
        : "+f"(d0), "+f"(d1), "+f"(d2), "+f"(d3)
        : "r"(a0), "r"(a1), "r"(a2), "r"(a3), "r"(b0), "r"(b1));
}

// -------- GEMM1 (tf32 raw-bits, cp.async double-buffered, 512 threads) --------
// h1h[NN,128] = X[NN,256] @ W[256,128]; BM=128, BN=128, BK=16.
// 16 warps: 8 in M (16 rows each) x 2 in N (64 cols each).
#define LDA 20
#define LDB 136
#define NT (DIN / 16)   // 16 k-tiles
__global__ void __launch_bounds__(512)
k_gemm1(const float* __restrict__ X, const float* __restrict__ W) {
    __shared__ __align__(16) uint32_t Ah[2][128 * LDA];
    __shared__ __align__(16) uint32_t Bh[2][16 * LDB];

    int tid = threadIdx.x;
    int lane = tid & 31;
    int wid = tid >> 5;
    int wm = wid & 7;            // 0..7: rows wm*16 .. wm*16+15
    int wn = wid >> 3;           // 0..1: cols wn*64 .. wn*64+63
    int g = lane >> 2;
    int t = lane & 3;
    int r0 = blockIdx.x * 128;

    int arow = tid >> 2, ac4 = tid & 3;   // A: one cp.async per thread
    int brow = tid >> 5, bc4 = tid & 31;  // B: one cp.async per thread

    auto load_tile = [&](int it, int buf) {
        cp_async16(&Ah[buf][arow * LDA + ac4 * 4],
                   X + (size_t)(r0 + arow) * DIN + it * 16 + ac4 * 4,
                   r0 + arow < NN);
        cp_async16(&Bh[buf][brow * LDB + bc4 * 4],
                   W + (size_t)(it * 16 + brow) * DH + bc4 * 4, true);
    };

    float acc[8][4];
#pragma unroll
    for (int j = 0; j < 8; j++)
#pragma unroll
        for (int k = 0; k < 4; k++) acc[j][k] = 0.f;

    load_tile(0, 0);
    cp_commit();

    for (int it = 0; it < NT; it++) {
        int buf = it & 1;
        if (it + 1 < NT) {
            load_tile(it + 1, (it + 1) & 1);
            cp_commit();
            cp_wait<1>();
        } else {
            cp_wait<0>();
        }
        __syncthreads();

#pragma unroll
        for (int kk = 0; kk < 2; kk++) {
            int kb = kk * 8;
            int rbase = (wm * 16) * LDA + kb + t;
            uint32_t a0 = Ah[buf][rbase + g * LDA];
            uint32_t a1 = Ah[buf][rbase + (g + 8) * LDA];
            uint32_t a2 = Ah[buf][rbase + g * LDA + 4];
            uint32_t a3 = Ah[buf][rbase + (g + 8) * LDA + 4];
            uint32_t bh[8][2];
#pragma unroll
            for (int nt = 0; nt < 8; nt++) {
                int cbase = wn * 64 + nt * 8 + g;
                bh[nt][0] = Bh[buf][(kb + t) * LDB + cbase];
                bh[nt][1] = Bh[buf][(kb + t + 4) * LDB + cbase];
            }
#pragma unroll
            for (int nt = 0; nt < 8; nt++) {
                float* d = acc[nt];
                mma_tf32(d[0], d[1], d[2], d[3], a0, a1, a2, a3, bh[nt][0], bh[nt][1]);
            }
        }
        __syncthreads();
    }

#pragma unroll
    for (int nt = 0; nt < 8; nt++) {
        int col = wn * 64 + nt * 8 + 2 * t;
        int rowa = r0 + wm * 16 + g;
        int rowb = rowa + 8;
        float* d = acc[nt];
        if (rowa < NN)
            *(__half2*)(g_h1h + (size_t)rowa * DH + col) = __floats2half2_rn(d[0], d[1]);
        if (rowb < NN)
            *(__half2*)(g_h1h + (size_t)rowb * DH + col) = __floats2half2_rn(d[2], d[3]);
    }
}

// -------- layer1 aggregation + bias + relu -> fp16: warp per node --------
__global__ void k_agg1(const float* __restrict__ B1) {
    int t = blockIdx.x * blockDim.x + threadIdx.x;
    int w = t >> 5, lane = t & 31;
    if (w >= NN) return;
    float dv = g_dinv[w];
    float c0 = dv * dv;
    const uint2* __restrict__ Hh = (const uint2*)g_h1h;
    uint2 us = Hh[(size_t)w * 32 + lane];
    float2 s0 = __half22float2(*(__half2*)&us.x);
    float2 s1 = __half22float2(*(__half2*)&us.y);
    float4 acc = make_float4(c0 * s0.x, c0 * s0.y, c0 * s1.x, c0 * s1.y);

    int j = g_off[w];
    int end = j + g_deg[w];
    for (; j + 2 <= end; j += 2) {
        unsigned e0 = g_edge[j], e1 = g_edge[j + 1];
        int sa, sb; float ca, cb;
        unpack_edge(e0, sa, ca);
        unpack_edge(e1, sb, cb);
        uint2 u0 = Hh[(size_t)sa * 32 + lane];
        uint2 u1 = Hh[(size_t)sb * 32 + lane];
        float2 a0 = __half22float2(*(__half2*)&u0.x);
        float2 a1 = __half22float2(*(__half2*)&u0.y);
        float2 b0 = __half22float2(*(__half2*)&u1.x);
        float2 b1 = __half22float2(*(__half2*)&u1.y);
        acc.x += ca * a0.x + cb * b0.x;
        acc.y += ca * a0.y + cb * b0.y;
        acc.z += ca * a1.x + cb * b1.x;
        acc.w += ca * a1.y + cb * b1.y;
    }
    if (j < end) {
        int sa; float ca;
        unpack_edge(g_edge[j], sa, ca);
        uint2 u0 = Hh[(size_t)sa * 32 + lane];
        float2 a0 = __half22float2(*(__half2*)&u0.x);
        float2 a1 = __half22float2(*(__half2*)&u0.y);
        acc.x += ca * a0.x; acc.y += ca * a0.y;
        acc.z += ca * a1.x; acc.w += ca * a1.y;
    }
    float4 bb = ((const float4*)B1)[lane];
    acc.x = fmaxf(acc.x + bb.x, 0.f);
    acc.y = fmaxf(acc.y + bb.y, 0.f);
    acc.z = fmaxf(acc.z + bb.z, 0.f);
    acc.w = fmaxf(acc.w + bb.w, 0.f);
    __half2 h01 = __floats2half2_rn(acc.x, acc.y);
    __half2 h23 = __floats2half2_rn(acc.z, acc.w);
    uint2 st;
    st.x = *(unsigned*)&h01;
    st.y = *(unsigned*)&h23;
    ((uint2*)g_a1h)[(size_t)w * 32 + lane] = st;
}

// -------- GEMM2: h2h[NN,40] = a1h[NN,128] @ W2[128,40] --------
// BM=256, BK=32, 256 threads, micro-tile 8x5
__global__ void k_gemm2(const float* __restrict__ W2) {
    __shared__ __align__(16) float As[256][33];
    __shared__ float Bs[32][40];
    int tid = threadIdx.x;
    int r0 = blockIdx.x * 256;
    int tx = tid & 7;    // 5 cols each
    int ty = tid >> 3;   // 8 rows each (0..31)
    float acc[8][5];
#pragma unroll
    for (int i = 0; i < 8; i++)
#pragma unroll
        for (int c = 0; c < 5; c++) acc[i][c] = 0.f;

    for (int kt = 0; kt < DH; kt += 32) {
        // A tile: 256x32 halfs -> fp32 smem; 2048 float4-groups, 8 per thread
#pragma unroll
        for (int q = 0; q < 8; q++) {
            int id = tid + q * 256;
            int row = id >> 3, c4 = id & 7;
            float4 v = make_float4(0.f, 0.f, 0.f, 0.f);
            if (r0 + row < NN) {
                uint2 u = *(const uint2*)(g_a1h + (size_t)(r0 + row) * DH + kt + c4 * 4);
                float2 f0 = __half22float2(*(__half2*)&u.x);
                float2 f1 = __half22float2(*(__half2*)&u.y);
                v = make_float4(f0.x, f0.y, f1.x, f1.y);
            }
            As[row][c4 * 4 + 0] = v.x; As[row][c4 * 4 + 1] = v.y;
            As[row][c4 * 4 + 2] = v.z; As[row][c4 * 4 + 3] = v.w;
        }
        // B tile: 32x40 = 1280 floats, 5 per thread
#pragma unroll
        for (int q = 0; q < 5; q++) {
            int id = tid + q * 256;
            int k = id / 40, c = id % 40;
            Bs[k][c] = W2[(size_t)(kt + k) * DO + c];
        }
        __syncthreads();
#pragma unroll 4
        for (int k = 0; k < 32; k++) {
            float b[5];
#pragma unroll
            for (int c = 0; c < 5; c++) b[c] = Bs[k][tx * 5 + c];
#pragma unroll
            for (int i = 0; i < 8; i++) {
                float a = As[ty * 8 + i][k];
#pragma unroll
                for (int c = 0; c < 5; c++) acc[i][c] += a * b[c];
            }
        }
        __syncthreads();
    }
#pragma unroll
    for (int i = 0; i < 8; i++) {
        int row = r0 + ty * 8 + i;
        if (row < NN) {
#pragma unroll
            for (int c = 0; c < 5; c++)
                g_h2h[(size_t)row * DO + tx * 5 + c] = __float2half_rn(acc[i][c]);
        }
    }
}

// -------- layer2 aggregation + bias + log_softmax fused --------
__global__ void k_agg2_logsm(float* __restrict__ out, const float* __restrict__ B2) {
    int t = blockIdx.x * blockDim.x + threadIdx.x;
    int w = t >> 5, lane = t & 31;
    if (w >= NN) return;
    bool act = lane < 20;
    float dv = g_dinv[w];
    float c0 = dv * dv;
    const __half2* __restrict__ Hh = (const __half2*)g_h2h;
    float acc0 = 0.f, acc1 = 0.f;
    if (act) {
        float2 f = __half22float2(Hh[(size_t)w * 20 + lane]);
        acc0 = c0 * f.x;
        acc1 = c0 * f.y;
    }
    int j = g_off[w];
    int end = j + g_deg[w];
    for (; j + 2 <= end; j += 2) {
        unsigned e0 = g_edge[j], e1 = g_edge[j + 1];
        if (act) {
            int sa, sb; float ca, cb;
            unpack_edge(e0, sa, ca);
            unpack_edge(e1, sb, cb);
            float2 f0 = __half22float2(Hh[(size_t)sa * 20 + lane]);
            float2 f1 = __half22float2(Hh[(size_t)sb * 20 + lane]);
            acc0 += ca * f0.x + cb * f1.x;
            acc1 += ca * f0.y + cb * f1.y;
        }
    }
    if (j < end) {
        unsigned e0 = g_edge[j];
        if (act) {
            int sa; float ca;
            unpack_edge(e0, sa, ca);
            float2 f0 = __half22float2(Hh[(size_t)sa * 20 + lane]);
            acc0 += ca * f0.x;
            acc1 += ca * f0.y;
        }
    }
    if (act) {
        acc0 += B2[2 * lane];
        acc1 += B2[2 * lane + 1];
    }
    float m = act ? fmaxf(acc0, acc1) : __int_as_float(0xff800000);
#pragma unroll
    for (int o = 16; o > 0; o >>= 1) m = fmaxf(m, __shfl_xor_sync(0xffffffffu, m, o));
    float s = act ? (expf(acc0 - m) + expf(acc1 - m)) : 0.f;
#pragma unroll
    for (int o = 16; o > 0; o >>= 1) s += __shfl_xor_sync(0xffffffffu, s, o);
    float lse = m + logf(s);
    if (act)
        *(float2*)(out + (size_t)w * DO + 2 * lane) = make_float2(acc0 - lse, acc1 - lse);
}

// -------- launch --------
extern "C" void kernel_launch(void* const* d_in, const int* in_sizes, int n_in,
                              void* d_out, int out_size) {
    const float* x  = (const float*)d_in[0];
    const void*  ei = d_in[1];
    const float* W1 = (const float*)d_in[2];
    const float* b1 = (const float*)d_in[3];
    const float* W2 = (const float*)d_in[4];
    const float* b2 = (const float*)d_in[5];
    float* out = (float*)d_out;

    (void)in_sizes; (void)n_in; (void)out_size;

    k_init<<<(NN + 255) / 256 + 1, 256>>>((const int*)ei);          // 0
    k_deg<<<(NE / 4 + 255) / 256, 256>>>(ei);                       // 1
    k_scan_block<<<SCAN_NB, SCAN_BLK>>>();                          // 2
    k_gemm1<<<(NN + 127) / 128, 512>>>(x, W1);                      // 3  <- ncu capture slot
    k_scan_fix<<<(NN + 255) / 256, 256>>>();                        // 4
    k_scatter<<<(NE / 4 + 255) / 256, 256>>>(ei);                   // 5
    k_agg1<<<(int)(((size_t)NN * 32 + 255) / 256), 256>>>(b1);      // 6
    k_gemm2<<<(NN + 255) / 256, 256>>>(W2);                         // 7
    k_agg2_logsm<<<(int)(((size_t)NN * 32 + 255) / 256), 256>>>(out, b2);  // 8
}

// round 9
// speedup vs baseline: 1.1316x; 1.1316x over previous
#include <cuda_runtime.h>
#include <cuda_fp16.h>
#include <cstdint>

#define NN 50000
#define NE 1600000
#define DIN 256
#define DH 128
#define DO 40

#define SCAN_BLK 512
#define SCAN_NB ((NN + SCAN_BLK - 1) / SCAN_BLK)   // 98

#define GEMM1_BLOCKS ((NN + 127) / 128)            // 391
#define SCAT_BLOCKS ((NE / 4 + 255) / 256)         // 1563

// -------- scratch (static device globals; no allocation allowed) --------
static __device__ __align__(16) __half g_h1h[(size_t)NN * DH];   // x@W1 (fp16, gather source)
static __device__ __align__(16) __half g_a1h[(size_t)NN * DH];   // relu(agg1+b1) (fp16)
static __device__ __align__(16) __half g_h2h[(size_t)NN * DO];   // layer2 pre-agg (fp16)
static __device__ int      g_deg[NN];
static __device__ float    g_dinv[NN];
static __device__ int      g_off[NN];
static __device__ int      g_pos[NN];
static __device__ int      g_inc[SCAN_NB * SCAN_BLK];
static __device__ int      g_bsum[SCAN_NB];
static __device__ unsigned g_edge[NE];   // packed: (src << 16) | fp16(coef)
static __device__ int      g_is64;

// -------- edge index accessors (dtype-agnostic) --------
__device__ __forceinline__ int e_src(const void* ei, int t) {
    return g_is64 ? (int)((const long long*)ei)[t] : ((const int*)ei)[t];
}
__device__ __forceinline__ int e_dst(const void* ei, int t) {
    return g_is64 ? (int)((const long long*)ei)[NE + t] : ((const int*)ei)[NE + t];
}

// -------- init: zero degree counters + detect edge dtype --------
__global__ void k_init(const int* __restrict__ ei32) {
    if (blockIdx.x == gridDim.x - 1) {
        int t = threadIdx.x;
        if (t == 0) g_is64 = 1;
        __syncthreads();
        int any = 0;
        for (int i = t; i < 2048; i += blockDim.x) any |= ei32[2 * i + 1];
        if (any) g_is64 = 0;
        return;
    }
    int t = blockIdx.x * blockDim.x + threadIdx.x;
    if (t < NN) g_deg[t] = 0;
}

// -------- degree histogram: 4 edges/thread on int32 path --------
__global__ void k_deg(const void* __restrict__ ei) {
    int t = blockIdx.x * blockDim.x + threadIdx.x;
    if (!g_is64) {
        if (t < NE / 4) {
            int4 d4 = ((const int4*)((const int*)ei + NE))[t];
            if ((unsigned)d4.x < NN) atomicAdd(&g_deg[d4.x], 1);
            if ((unsigned)d4.y < NN) atomicAdd(&g_deg[d4.y], 1);
            if ((unsigned)d4.z < NN) atomicAdd(&g_deg[d4.z], 1);
            if ((unsigned)d4.w < NN) atomicAdd(&g_deg[d4.w], 1);
        }
    } else {
        for (int e = t * 4; e < t * 4 + 4 && e < NE; e++) {
            int d = (int)((const long long*)ei)[NE + e];
            if ((unsigned)d < NN) atomicAdd(&g_deg[d], 1);
        }
    }
}

// -------- scan level 1: per-block inclusive scan --------
__global__ void k_scan_block() {
    __shared__ int sh[SCAN_BLK];
    int t = threadIdx.x;
    int i = blockIdx.x * SCAN_BLK + t;
    int v = (i < NN) ? g_deg[i] : 0;
    sh[t] = v;
    __syncthreads();
#pragma unroll
    for (int o = 1; o < SCAN_BLK; o <<= 1) {
        int x = (t >= o) ? sh[t - o] : 0;
        __syncthreads();
        sh[t] += x;
        __syncthreads();
    }
    g_inc[i] = sh[t];
    if (t == SCAN_BLK - 1) g_bsum[blockIdx.x] = sh[t];
}

// -------- scan fix (+ in-block top scan) + dinv --------
__global__ void k_scan_fix() {
    __shared__ int sb[SCAN_NB];
    if (threadIdx.x == 0) {
        int run = 0;
        for (int i = 0; i < SCAN_NB; i++) { sb[i] = run; run += g_bsum[i]; }
    }
    __syncthreads();
    int t = blockIdx.x * blockDim.x + threadIdx.x;
    if (t < NN) {
        int dg = g_deg[t];
        int off = g_inc[t] - dg + sb[t / SCAN_BLK];  // exclusive
        g_off[t] = off;
        g_pos[t] = off;
        g_dinv[t] = rsqrtf((float)(dg + 1));
    }
}

__device__ __forceinline__ void unpack_edge(unsigned e, int& s, float& c) {
    s = (int)(e >> 16);
    c = __half2float(__ushort_as_half((unsigned short)(e & 0xffffu)));
}

// -------- async copy helpers --------
__device__ __forceinline__ void cp_async16(void* smem, const void* gmem, bool pred) {
    uint32_t sa = (uint32_t)__cvta_generic_to_shared(smem);
    int sz = pred ? 16 : 0;
    asm volatile("cp.async.cg.shared.global [%0], [%1], 16, %2;" :: "r"(sa), "l"(gmem), "r"(sz));
}
__device__ __forceinline__ void cp_commit() { asm volatile("cp.async.commit_group;"); }
template <int N>
__device__ __forceinline__ void cp_wait() { asm volatile("cp.async.wait_group %0;" :: "n"(N)); }

__device__ __forceinline__ void mma_tf32(float& d0, float& d1, float& d2, float& d3,
                                         uint32_t a0, uint32_t a1, uint32_t a2, uint32_t a3,
                                         uint32_t b0, uint32_t b1) {
    asm volatile(
        "mma.sync.aligned.m16n8k8.row.col.f32.tf32.tf32.f32 "
        "{%0,%1,%2,%3}, {%4,%5,%6,%7}, {%8,%9}, {%0,%1,%2,%3};"
        : "+f"(d0), "+f"(d1), "+f"(d2), "+f"(d3)
        : "r"(a0), "r"(a1), "r"(a2), "r"(a3), "r"(b0), "r"(b1));
}

// ======== COMBINED LAUNCH: blocks [0,391) = GEMM1, blocks [391,...) = scatter ========
// GEMM1 (tf32 raw-bits, cp.async double-buffered, 256 threads; R7 config):
// h1h[NN,128] = X[NN,256] @ W[256,128]; BM=128, BN=128, BK=16; 8 warps 4Mx2N.
#define LDA 20
#define LDB 136
#define NT (DIN / 16)   // 16 k-tiles

__device__ void gemm1_body(const float* __restrict__ X, const float* __restrict__ W,
                           int bid) {
    __shared__ __align__(16) uint32_t Ah[2][128 * LDA];
    __shared__ __align__(16) uint32_t Bh[2][16 * LDB];

    int tid = threadIdx.x;
    int lane = tid & 31;
    int wid = tid >> 5;
    int wm = wid & 3;
    int wn = wid >> 2;
    int g = lane >> 2;
    int t = lane & 3;
    int r0 = bid * 128;

    int arow = tid >> 2, ac4 = tid & 3;
    int brow = tid >> 5, bc4 = tid & 31;

    auto load_tile = [&](int it, int buf) {
#pragma unroll
        for (int q = 0; q < 2; q++) {
            int row = arow + q * 64;
            cp_async16(&Ah[buf][row * LDA + ac4 * 4],
                       X + (size_t)(r0 + row) * DIN + it * 16 + ac4 * 4,
                       r0 + row < NN);
        }
#pragma unroll
        for (int q = 0; q < 2; q++) {
            int kr = brow + q * 8;
            cp_async16(&Bh[buf][kr * LDB + bc4 * 4],
                       W + (size_t)(it * 16 + kr) * DH + bc4 * 4, true);
        }
    };

    float acc[2][8][4];
#pragma unroll
    for (int i = 0; i < 2; i++)
#pragma unroll
        for (int j = 0; j < 8; j++)
#pragma unroll
            for (int k = 0; k < 4; k++) acc[i][j][k] = 0.f;

    load_tile(0, 0);
    cp_commit();

    for (int it = 0; it < NT; it++) {
        int buf = it & 1;
        if (it + 1 < NT) {
            load_tile(it + 1, (it + 1) & 1);
            cp_commit();
            cp_wait<1>();
        } else {
            cp_wait<0>();
        }
        __syncthreads();

#pragma unroll
        for (int kk = 0; kk < 2; kk++) {
            int kb = kk * 8;
            uint32_t ah[2][4];
#pragma unroll
            for (int mt = 0; mt < 2; mt++) {
                int rbase = (wm * 32 + mt * 16) * LDA + kb + t;
                ah[mt][0] = Ah[buf][rbase + g * LDA];
                ah[mt][1] = Ah[buf][rbase + (g + 8) * LDA];
                ah[mt][2] = Ah[buf][rbase + g * LDA + 4];
                ah[mt][3] = Ah[buf][rbase + (g + 8) * LDA + 4];
            }
            uint32_t bh[8][2];
#pragma unroll
            for (int nt = 0; nt < 8; nt++) {
                int cbase = wn * 64 + nt * 8 + g;
                bh[nt][0] = Bh[buf][(kb + t) * LDB + cbase];
                bh[nt][1] = Bh[buf][(kb + t + 4) * LDB + cbase];
            }
#pragma unroll
            for (int mt = 0; mt < 2; mt++)
#pragma unroll
                for (int nt = 0; nt < 8; nt++) {
                    float* d = acc[mt][nt];
                    mma_tf32(d[0], d[1], d[2], d[3],
                             ah[mt][0], ah[mt][1], ah[mt][2], ah[mt][3],
                             bh[nt][0], bh[nt][1]);
                }
        }
        __syncthreads();
    }

#pragma unroll
    for (int mt = 0; mt < 2; mt++) {
#pragma unroll
        for (int nt = 0; nt < 8; nt++) {
            int col = wn * 64 + nt * 8 + 2 * t;
            int rowa = r0 + wm * 32 + mt * 16 + g;
            int rowb = rowa + 8;
            float* d = acc[mt][nt];
            if (rowa < NN)
                *(__half2*)(g_h1h + (size_t)rowa * DH + col) = __floats2half2_rn(d[0], d[1]);
            if (rowb < NN)
                *(__half2*)(g_h1h + (size_t)rowb * DH + col) = __floats2half2_rn(d[2], d[3]);
        }
    }
}

__device__ void scatter_body(const void* __restrict__ ei, int bid) {
    int t = bid * 256 + threadIdx.x;
    if (!g_is64) {
        if (t < NE / 4) {
            int4 s4 = ((const int4*)ei)[t];
            int4 d4 = ((const int4*)((const int*)ei + NE))[t];
            int ss[4] = {s4.x, s4.y, s4.z, s4.w};
            int dd[4] = {d4.x, d4.y, d4.z, d4.w};
#pragma unroll
            for (int q = 0; q < 4; q++) {
                int s = ss[q], d = dd[q];
                if ((unsigned)s < NN && (unsigned)d < NN) {
                    int slot = atomicAdd(&g_pos[d], 1);
                    unsigned hb = __half_as_ushort(__float2half_rn(g_dinv[s] * g_dinv[d]));
                    g_edge[slot] = ((unsigned)s << 16) | hb;
                }
            }
        }
    } else {
        for (int e = t * 4; e < t * 4 + 4 && e < NE; e++) {
            int s = (int)((const long long*)ei)[e];
            int d = (int)((const long long*)ei)[NE + e];
            if ((unsigned)s < NN && (unsigned)d < NN) {
                int slot = atomicAdd(&g_pos[d], 1);
                unsigned hb = __half_as_ushort(__float2half_rn(g_dinv[s] * g_dinv[d]));
                g_edge[slot] = ((unsigned)s << 16) | hb;
            }
        }
    }
}

__global__ void __launch_bounds__(256)
k_gemm1_scatter(const float* __restrict__ X, const float* __restrict__ W,
                const void* __restrict__ ei) {
    if (blockIdx.x < GEMM1_BLOCKS)
        gemm1_body(X, W, blockIdx.x);
    else
        scatter_body(ei, blockIdx.x - GEMM1_BLOCKS);
}

// -------- layer1 aggregation + bias + relu -> fp16: warp per node, 4x unroll --------
__global__ void k_agg1(const float* __restrict__ B1) {
    int t = blockIdx.x * blockDim.x + threadIdx.x;
    int w = t >> 5, lane = t & 31;
    if (w >= NN) return;
    float dv = g_dinv[w];
    float c0 = dv * dv;
    const uint2* __restrict__ Hh = (const uint2*)g_h1h;
    uint2 us = Hh[(size_t)w * 32 + lane];
    float2 s0 = __half22float2(*(__half2*)&us.x);
    float2 s1 = __half22float2(*(__half2*)&us.y);
    float4 acc = make_float4(c0 * s0.x, c0 * s0.y, c0 * s1.x, c0 * s1.y);

    int j = g_off[w];
    int end = j + g_deg[w];
    for (; j + 4 <= end; j += 4) {
        unsigned ew[4];
#pragma unroll
        for (int q = 0; q < 4; q++) ew[q] = g_edge[j + q];
        uint2 u[4];
#pragma unroll
        for (int q = 0; q < 4; q++) u[q] = Hh[(size_t)(ew[q] >> 16) * 32 + lane];
#pragma unroll
        for (int q = 0; q < 4; q++) {
            float c = __half2float(__ushort_as_half((unsigned short)(ew[q] & 0xffffu)));
            float2 f0 = __half22float2(*(__half2*)&u[q].x);
            float2 f1 = __half22float2(*(__half2*)&u[q].y);
            acc.x += c * f0.x; acc.y += c * f0.y;
            acc.z += c * f1.x; acc.w += c * f1.y;
        }
    }
    for (; j < end; j++) {
        int sa; float ca;
        unpack_edge(g_edge[j], sa, ca);
        uint2 u0 = Hh[(size_t)sa * 32 + lane];
        float2 a0 = __half22float2(*(__half2*)&u0.x);
        float2 a1 = __half22float2(*(__half2*)&u0.y);
        acc.x += ca * a0.x; acc.y += ca * a0.y;
        acc.z += ca * a1.x; acc.w += ca * a1.y;
    }
    float4 bb = ((const float4*)B1)[lane];
    acc.x = fmaxf(acc.x + bb.x, 0.f);
    acc.y = fmaxf(acc.y + bb.y, 0.f);
    acc.z = fmaxf(acc.z + bb.z, 0.f);
    acc.w = fmaxf(acc.w + bb.w, 0.f);
    __half2 h01 = __floats2half2_rn(acc.x, acc.y);
    __half2 h23 = __floats2half2_rn(acc.z, acc.w);
    uint2 st;
    st.x = *(unsigned*)&h01;
    st.y = *(unsigned*)&h23;
    ((uint2*)g_a1h)[(size_t)w * 32 + lane] = st;
}

// -------- GEMM2 (R7 config): h2h[NN,40] = a1h[NN,128] @ W2[128,40] --------
__global__ void k_gemm2(const float* __restrict__ W2) {
    __shared__ __align__(16) float As[128][65];
    __shared__ float Bs[64][40];
    int tid = threadIdx.x;
    int r0 = blockIdx.x * 128;
    int tx = tid & 7;
    int ty = tid >> 3;
    float acc[4][5];
#pragma unroll
    for (int i = 0; i < 4; i++)
#pragma unroll
        for (int c = 0; c < 5; c++) acc[i][c] = 0.f;

    for (int kt = 0; kt < DH; kt += 64) {
#pragma unroll
        for (int q = 0; q < 8; q++) {
            int id = tid + q * 256;
            int row = id >> 4, c4 = id & 15;
            float4 v = make_float4(0.f, 0.f, 0.f, 0.f);
            if (r0 + row < NN) {
                uint2 u = *(const uint2*)(g_a1h + (size_t)(r0 + row) * DH + kt + c4 * 4);
                float2 f0 = __half22float2(*(__half2*)&u.x);
                float2 f1 = __half22float2(*(__half2*)&u.y);
                v = make_float4(f0.x, f0.y, f1.x, f1.y);
            }
            As[row][c4 * 4 + 0] = v.x; As[row][c4 * 4 + 1] = v.y;
            As[row][c4 * 4 + 2] = v.z; As[row][c4 * 4 + 3] = v.w;
        }
#pragma unroll
        for (int q = 0; q < 10; q++) {
            int id = tid + q * 256;
            int k = id / 40, c = id % 40;
            Bs[k][c] = W2[(size_t)(kt + k) * DO + c];
        }
        __syncthreads();
#pragma unroll 8
        for (int k = 0; k < 64; k++) {
            float b[5];
#pragma unroll
            for (int c = 0; c < 5; c++) b[c] = Bs[k][tx * 5 + c];
#pragma unroll
            for (int i = 0; i < 4; i++) {
                float a = As[ty * 4 + i][k];
#pragma unroll
                for (int c = 0; c < 5; c++) acc[i][c] += a * b[c];
            }
        }
        __syncthreads();
    }
#pragma unroll
    for (int i = 0; i < 4; i++) {
        int row = r0 + ty * 4 + i;
        if (row < NN) {
#pragma unroll
            for (int c = 0; c < 5; c++)
                g_h2h[(size_t)row * DO + tx * 5 + c] = __float2half_rn(acc[i][c]);
        }
    }
}

// -------- layer2 aggregation + bias + log_softmax fused, 4x unroll --------
__global__ void k_agg2_logsm(float* __restrict__ out, const float* __restrict__ B2) {
    int t = blockIdx.x * blockDim.x + threadIdx.x;
    int w = t >> 5, lane = t & 31;
    if (w >= NN) return;
    bool act = lane < 20;
    float dv = g_dinv[w];
    float c0 = dv * dv;
    const __half2* __restrict__ Hh = (const __half2*)g_h2h;
    float acc0 = 0.f, acc1 = 0.f;
    if (act) {
        float2 f = __half22float2(Hh[(size_t)w * 20 + lane]);
        acc0 = c0 * f.x;
        acc1 = c0 * f.y;
    }
    int j = g_off[w];
    int end = j + g_deg[w];
    int lidx = act ? lane : 0;
    for (; j + 4 <= end; j += 4) {
        unsigned ew[4];
#pragma unroll
        for (int q = 0; q < 4; q++) ew[q] = g_edge[j + q];
        __half2 u[4];
#pragma unroll
        for (int q = 0; q < 4; q++) u[q] = Hh[(size_t)(ew[q] >> 16) * 20 + lidx];
        if (act) {
#pragma unroll
            for (int q = 0; q < 4; q++) {
                float c = __half2float(__ushort_as_half((unsigned short)(ew[q] & 0xffffu)));
                float2 f = __half22float2(u[q]);
                acc0 += c * f.x;
                acc1 += c * f.y;
            }
        }
    }
    for (; j < end; j++) {
        unsigned e0 = g_edge[j];
        float2 f = __half22float2(Hh[(size_t)(e0 >> 16) * 20 + lidx]);
        if (act) {
            float c = __half2float(__ushort_as_half((unsigned short)(e0 & 0xffffu)));
            acc0 += c * f.x;
            acc1 += c * f.y;
        }
    }
    if (act) {
        acc0 += B2[2 * lane];
        acc1 += B2[2 * lane + 1];
    }
    float m = act ? fmaxf(acc0, acc1) : __int_as_float(0xff800000);
#pragma unroll
    for (int o = 16; o > 0; o >>= 1) m = fmaxf(m, __shfl_xor_sync(0xffffffffu, m, o));
    float s = act ? (expf(acc0 - m) + expf(acc1 - m)) : 0.f;
#pragma unroll
    for (int o = 16; o > 0; o >>= 1) s += __shfl_xor_sync(0xffffffffu, s, o);
    float lse = m + logf(s);
    if (act)
        *(float2*)(out + (size_t)w * DO + 2 * lane) = make_float2(acc0 - lse, acc1 - lse);
}

// -------- launch --------
extern "C" void kernel_launch(void* const* d_in, const int* in_sizes, int n_in,
                              void* d_out, int out_size) {
    const float* x  = (const float*)d_in[0];
    const void*  ei = d_in[1];
    const float* W1 = (const float*)d_in[2];
    const float* b1 = (const float*)d_in[3];
    const float* W2 = (const float*)d_in[4];
    const float* b2 = (const float*)d_in[5];
    float* out = (float*)d_out;

    (void)in_sizes; (void)n_in; (void)out_size;

    k_init<<<(NN + 255) / 256 + 1, 256>>>((const int*)ei);                 // 0
    k_deg<<<(NE / 4 + 255) / 256, 256>>>(ei);                              // 1
    k_scan_block<<<SCAN_NB, SCAN_BLK>>>();                                 // 2
    k_scan_fix<<<(NN + 255) / 256, 256>>>();                               // 3
    k_gemm1_scatter<<<GEMM1_BLOCKS + SCAT_BLOCKS, 256>>>(x, W1, ei);       // 4 (overlapped)
    k_agg1<<<(int)(((size_t)NN * 32 + 255) / 256), 256>>>(b1);             // 5
    k_gemm2<<<(NN + 127) / 128, 256>>>(W2);                                // 6
    k_agg2_logsm<<<(int)(((size_t)NN * 32 + 255) / 256), 256>>>(out, b2);  // 7
}

// round 10
// speedup vs baseline: 1.1927x; 1.0540x over previous
#include <cuda_runtime.h>
#include <cuda_fp16.h>
#include <cstdint>

#define NN 50000
#define NE 1600000
#define DIN 256
#define DH 128
#define DO 40

#define SCAN_BLK 512
#define SCAN_NB ((NN + SCAN_BLK - 1) / SCAN_BLK)   // 98

#define GEMM1_BLOCKS ((NN + 127) / 128)            // 391
#define DEG_BLOCKS ((NE / 4 + 255) / 256)          // 1563

// -------- scratch (static device globals; no allocation allowed) --------
static __device__ __align__(16) __half g_h1h[(size_t)NN * DH];   // x@W1 (fp16, gather source)
static __device__ __align__(16) __half g_a1h[(size_t)NN * DH];   // relu(agg1+b1) (fp16)
static __device__ __align__(16) __half g_h2h[(size_t)NN * DO];   // layer2 pre-agg (fp16)
static __device__ int      g_deg[NN];
static __device__ float    g_dinv[NN];
static __device__ int      g_off[NN];
static __device__ int      g_pos[NN];
static __device__ unsigned g_edge[NE];   // packed: (src << 16) | fp16(coef)
static __device__ int      g_is64;
static __device__ int      g_total;      // scan ticket (self-resetting)
static __device__ int      g_done;       // scan completion counter (self-resetting)

// -------- init: zero degree counters + detect edge dtype --------
__global__ void k_init(const int* __restrict__ ei32) {
    if (blockIdx.x == gridDim.x - 1) {
        int t = threadIdx.x;
        if (t == 0) g_is64 = 1;
        __syncthreads();
        int any = 0;
        for (int i = t; i < 2048; i += blockDim.x) any |= ei32[2 * i + 1];
        if (any) g_is64 = 0;
        return;
    }
    int t = blockIdx.x * blockDim.x + threadIdx.x;
    if (t < NN) g_deg[t] = 0;
}

// -------- async copy helpers --------
__device__ __forceinline__ void cp_async16(void* smem, const void* gmem, bool pred) {
    uint32_t sa = (uint32_t)__cvta_generic_to_shared(smem);
    int sz = pred ? 16 : 0;
    asm volatile("cp.async.cg.shared.global [%0], [%1], 16, %2;" :: "r"(sa), "l"(gmem), "r"(sz));
}
__device__ __forceinline__ void cp_commit() { asm volatile("cp.async.commit_group;"); }
template <int N>
__device__ __forceinline__ void cp_wait() { asm volatile("cp.async.wait_group %0;" :: "n"(N)); }

__device__ __forceinline__ void mma_tf32(float& d0, float& d1, float& d2, float& d3,
                                         uint32_t a0, uint32_t a1, uint32_t a2, uint32_t a3,
                                         uint32_t b0, uint32_t b1) {
    asm volatile(
        "mma.sync.aligned.m16n8k8.row.col.f32.tf32.tf32.f32 "
        "{%0,%1,%2,%3}, {%4,%5,%6,%7}, {%8,%9}, {%0,%1,%2,%3};"
        : "+f"(d0), "+f"(d1), "+f"(d2), "+f"(d3)
        : "r"(a0), "r"(a1), "r"(a2), "r"(a3), "r"(b0), "r"(b1));
}

// ======== COMBINED LAUNCH 1: blocks [0,391) = GEMM1, blocks [391,...) = degree ========
#define LDA 20
#define LDB 136
#define NT (DIN / 16)   // 16 k-tiles

__device__ void gemm1_body(const float* __restrict__ X, const float* __restrict__ W,
                           int bid) {
    __shared__ __align__(16) uint32_t Ah[2][128 * LDA];
    __shared__ __align__(16) uint32_t Bh[2][16 * LDB];

    int tid = threadIdx.x;
    int lane = tid & 31;
    int wid = tid >> 5;
    int wm = wid & 3;
    int wn = wid >> 2;
    int g = lane >> 2;
    int t = lane & 3;
    int r0 = bid * 128;

    int arow = tid >> 2, ac4 = tid & 3;
    int brow = tid >> 5, bc4 = tid & 31;

    auto load_tile = [&](int it, int buf) {
#pragma unroll
        for (int q = 0; q < 2; q++) {
            int row = arow + q * 64;
            cp_async16(&Ah[buf][row * LDA + ac4 * 4],
                       X + (size_t)(r0 + row) * DIN + it * 16 + ac4 * 4,
                       r0 + row < NN);
        }
#pragma unroll
        for (int q = 0; q < 2; q++) {
            int kr = brow + q * 8;
            cp_async16(&Bh[buf][kr * LDB + bc4 * 4],
                       W + (size_t)(it * 16 + kr) * DH + bc4 * 4, true);
        }
    };

    float acc[2][8][4];
#pragma unroll
    for (int i = 0; i < 2; i++)
#pragma unroll
        for (int j = 0; j < 8; j++)
#pragma unroll
            for (int k = 0; k < 4; k++) acc[i][j][k] = 0.f;

    load_tile(0, 0);
    cp_commit();

    for (int it = 0; it < NT; it++) {
        int buf = it & 1;
        if (it + 1 < NT) {
            load_tile(it + 1, (it + 1) & 1);
            cp_commit();
            cp_wait<1>();
        } else {
            cp_wait<0>();
        }
        __syncthreads();

#pragma unroll
        for (int kk = 0; kk < 2; kk++) {
            int kb = kk * 8;
            uint32_t ah[2][4];
#pragma unroll
            for (int mt = 0; mt < 2; mt++) {
                int rbase = (wm * 32 + mt * 16) * LDA + kb + t;
                ah[mt][0] = Ah[buf][rbase + g * LDA];
                ah[mt][1] = Ah[buf][rbase + (g + 8) * LDA];
                ah[mt][2] = Ah[buf][rbase + g * LDA + 4];
                ah[mt][3] = Ah[buf][rbase + (g + 8) * LDA + 4];
            }
            uint32_t bh[8][2];
#pragma unroll
            for (int nt = 0; nt < 8; nt++) {
                int cbase = wn * 64 + nt * 8 + g;
                bh[nt][0] = Bh[buf][(kb + t) * LDB + cbase];
                bh[nt][1] = Bh[buf][(kb + t + 4) * LDB + cbase];
            }
#pragma unroll
            for (int mt = 0; mt < 2; mt++)
#pragma unroll
                for (int nt = 0; nt < 8; nt++) {
                    float* d = acc[mt][nt];
                    mma_tf32(d[0], d[1], d[2], d[3],
                             ah[mt][0], ah[mt][1], ah[mt][2], ah[mt][3],
                             bh[nt][0], bh[nt][1]);
                }
        }
        __syncthreads();
    }

#pragma unroll
    for (int mt = 0; mt < 2; mt++) {
#pragma unroll
        for (int nt = 0; nt < 8; nt++) {
            int col = wn * 64 + nt * 8 + 2 * t;
            int rowa = r0 + wm * 32 + mt * 16 + g;
            int rowb = rowa + 8;
            float* d = acc[mt][nt];
            if (rowa < NN)
                *(__half2*)(g_h1h + (size_t)rowa * DH + col) = __floats2half2_rn(d[0], d[1]);
            if (rowb < NN)
                *(__half2*)(g_h1h + (size_t)rowb * DH + col) = __floats2half2_rn(d[2], d[3]);
        }
    }
}

__device__ void deg_body(const void* __restrict__ ei, int bid) {
    int t = bid * 256 + threadIdx.x;
    if (!g_is64) {
        if (t < NE / 4) {
            int4 d4 = ((const int4*)((const int*)ei + NE))[t];
            if ((unsigned)d4.x < NN) atomicAdd(&g_deg[d4.x], 1);
            if ((unsigned)d4.y < NN) atomicAdd(&g_deg[d4.y], 1);
            if ((unsigned)d4.z < NN) atomicAdd(&g_deg[d4.z], 1);
            if ((unsigned)d4.w < NN) atomicAdd(&g_deg[d4.w], 1);
        }
    } else {
        for (int e = t * 4; e < t * 4 + 4 && e < NE; e++) {
            int d = (int)((const long long*)ei)[NE + e];
            if ((unsigned)d < NN) atomicAdd(&g_deg[d], 1);
        }
    }
}

__global__ void __launch_bounds__(256)
k_gemm1_deg(const float* __restrict__ X, const float* __restrict__ W,
            const void* __restrict__ ei) {
    if (blockIdx.x < GEMM1_BLOCKS)
        gemm1_body(X, W, blockIdx.x);
    else
        deg_body(ei, blockIdx.x - GEMM1_BLOCKS);
}

// -------- single-kernel ticket scan: g_off/g_pos/g_dinv from g_deg --------
// Block bases come from an atomic ticket (arrival-ordered): CSR ranges are
// disjoint and correctly sized, which is all correctness requires.
__global__ void k_scan() {
    __shared__ int sh[SCAN_BLK];
    __shared__ int base;
    int t = threadIdx.x;
    int i = blockIdx.x * SCAN_BLK + t;
    int v = (i < NN) ? g_deg[i] : 0;
    sh[t] = v;
    __syncthreads();
#pragma unroll
    for (int o = 1; o < SCAN_BLK; o <<= 1) {
        int x = (t >= o) ? sh[t - o] : 0;
        __syncthreads();
        sh[t] += x;
        __syncthreads();
    }
    if (t == SCAN_BLK - 1) base = atomicAdd(&g_total, sh[t]);
    __syncthreads();
    if (i < NN) {
        int off = base + sh[t] - v;   // exclusive within arrival-ordered layout
        g_off[i] = off;
        g_pos[i] = off;
        g_dinv[i] = rsqrtf((float)(v + 1));
    }
    // self-reset for next launch (after all blocks have taken their ticket)
    __threadfence();
    if (t == 0) {
        if (atomicAdd(&g_done, 1) == gridDim.x - 1) {
            g_total = 0;
            g_done = 0;
        }
    }
}

// -------- CSR fill: packed (src:16 | coef:fp16), 4 edges/thread --------
__global__ void k_scatter(const void* __restrict__ ei) {
    int t = blockIdx.x * blockDim.x + threadIdx.x;
    if (!g_is64) {
        if (t < NE / 4) {
            int4 s4 = ((const int4*)ei)[t];
            int4 d4 = ((const int4*)((const int*)ei + NE))[t];
            int ss[4] = {s4.x, s4.y, s4.z, s4.w};
            int dd[4] = {d4.x, d4.y, d4.z, d4.w};
#pragma unroll
            for (int q = 0; q < 4; q++) {
                int s = ss[q], d = dd[q];
                if ((unsigned)s < NN && (unsigned)d < NN) {
                    int slot = atomicAdd(&g_pos[d], 1);
                    unsigned hb = __half_as_ushort(__float2half_rn(g_dinv[s] * g_dinv[d]));
                    g_edge[slot] = ((unsigned)s << 16) | hb;
                }
            }
        }
    } else {
        for (int e = t * 4; e < t * 4 + 4 && e < NE; e++) {
            int s = (int)((const long long*)ei)[e];
            int d = (int)((const long long*)ei)[NE + e];
            if ((unsigned)s < NN && (unsigned)d < NN) {
                int slot = atomicAdd(&g_pos[d], 1);
                unsigned hb = __half_as_ushort(__float2half_rn(g_dinv[s] * g_dinv[d]));
                g_edge[slot] = ((unsigned)s << 16) | hb;
            }
        }
    }
}

// -------- layer1 aggregation: warp per node, half-warp per edge, uint4 gather --------
// lanes 0..15 handle edge j (cols 8l..8l+7 each), lanes 16..31 handle edge j+1.
__global__ void k_agg1(const float* __restrict__ B1) {
    int t = blockIdx.x * blockDim.x + threadIdx.x;
    int w = t >> 5, lane = t & 31;
    if (w >= NN) return;
    int half = lane >> 4;
    int l = lane & 15;
    const uint4* __restrict__ H4 = (const uint4*)g_h1h;   // row = 16 uint4
    float acc[8];
#pragma unroll
    for (int i = 0; i < 8; i++) acc[i] = 0.f;

    float dv = g_dinv[w];
    if (half == 0) {
        float c0 = dv * dv;
        uint4 u = H4[(size_t)w * 16 + l];
        float2 f0 = __half22float2(*(__half2*)&u.x);
        float2 f1 = __half22float2(*(__half2*)&u.y);
        float2 f2 = __half22float2(*(__half2*)&u.z);
        float2 f3 = __half22float2(*(__half2*)&u.w);
        acc[0] = c0 * f0.x; acc[1] = c0 * f0.y; acc[2] = c0 * f1.x; acc[3] = c0 * f1.y;
        acc[4] = c0 * f2.x; acc[5] = c0 * f2.y; acc[6] = c0 * f3.x; acc[7] = c0 * f3.y;
    }

    int j = g_off[w];
    int end = j + g_deg[w];
    for (; j + 4 <= end; j += 4) {
        unsigned ea = g_edge[j + half];
        unsigned eb = g_edge[j + 2 + half];
        uint4 ua = H4[(size_t)(ea >> 16) * 16 + l];
        uint4 ub = H4[(size_t)(eb >> 16) * 16 + l];
        float ca = __half2float(__ushort_as_half((unsigned short)(ea & 0xffffu)));
        float cb = __half2float(__ushort_as_half((unsigned short)(eb & 0xffffu)));
        {
            float2 f0 = __half22float2(*(__half2*)&ua.x);
            float2 f1 = __half22float2(*(__half2*)&ua.y);
            float2 f2 = __half22float2(*(__half2*)&ua.z);
            float2 f3 = __half22float2(*(__half2*)&ua.w);
            acc[0] += ca * f0.x; acc[1] += ca * f0.y; acc[2] += ca * f1.x; acc[3] += ca * f1.y;
            acc[4] += ca * f2.x; acc[5] += ca * f2.y; acc[6] += ca * f3.x; acc[7] += ca * f3.y;
        }
        {
            float2 f0 = __half22float2(*(__half2*)&ub.x);
            float2 f1 = __half22float2(*(__half2*)&ub.y);
            float2 f2 = __half22float2(*(__half2*)&ub.z);
            float2 f3 = __half22float2(*(__half2*)&ub.w);
            acc[0] += cb * f0.x; acc[1] += cb * f0.y; acc[2] += cb * f1.x; acc[3] += cb * f1.y;
            acc[4] += cb * f2.x; acc[5] += cb * f2.y; acc[6] += cb * f3.x; acc[7] += cb * f3.y;
        }
    }
    if (j + 2 <= end) {
        unsigned ea = g_edge[j + half];
        uint4 ua = H4[(size_t)(ea >> 16) * 16 + l];
        float ca = __half2float(__ushort_as_half((unsigned short)(ea & 0xffffu)));
        float2 f0 = __half22float2(*(__half2*)&ua.x);
        float2 f1 = __half22float2(*(__half2*)&ua.y);
        float2 f2 = __half22float2(*(__half2*)&ua.z);
        float2 f3 = __half22float2(*(__half2*)&ua.w);
        acc[0] += ca * f0.x; acc[1] += ca * f0.y; acc[2] += ca * f1.x; acc[3] += ca * f1.y;
        acc[4] += ca * f2.x; acc[5] += ca * f2.y; acc[6] += ca * f3.x; acc[7] += ca * f3.y;
        j += 2;
    }
    if (j < end && half == 0) {
        unsigned ea = g_edge[j];
        uint4 ua = H4[(size_t)(ea >> 16) * 16 + l];
        float ca = __half2float(__ushort_as_half((unsigned short)(ea & 0xffffu)));
        float2 f0 = __half22float2(*(__half2*)&ua.x);
        float2 f1 = __half22float2(*(__half2*)&ua.y);
        float2 f2 = __half22float2(*(__half2*)&ua.z);
        float2 f3 = __half22float2(*(__half2*)&ua.w);
        acc[0] += ca * f0.x; acc[1] += ca * f0.y; acc[2] += ca * f1.x; acc[3] += ca * f1.y;
        acc[4] += ca * f2.x; acc[5] += ca * f2.y; acc[6] += ca * f3.x; acc[7] += ca * f3.y;
    }

    // combine halves
#pragma unroll
    for (int i = 0; i < 8; i++) acc[i] += __shfl_xor_sync(0xffffffffu, acc[i], 16);

    if (half == 0) {
        float4 b0 = ((const float4*)B1)[2 * l];
        float4 b1v = ((const float4*)B1)[2 * l + 1];
        acc[0] = fmaxf(acc[0] + b0.x, 0.f); acc[1] = fmaxf(acc[1] + b0.y, 0.f);
        acc[2] = fmaxf(acc[2] + b0.z, 0.f); acc[3] = fmaxf(acc[3] + b0.w, 0.f);
        acc[4] = fmaxf(acc[4] + b1v.x, 0.f); acc[5] = fmaxf(acc[5] + b1v.y, 0.f);
        acc[6] = fmaxf(acc[6] + b1v.z, 0.f); acc[7] = fmaxf(acc[7] + b1v.w, 0.f);
        __half2 h0 = __floats2half2_rn(acc[0], acc[1]);
        __half2 h1 = __floats2half2_rn(acc[2], acc[3]);
        __half2 h2 = __floats2half2_rn(acc[4], acc[5]);
        __half2 h3 = __floats2half2_rn(acc[6], acc[7]);
        uint4 st;
        st.x = *(unsigned*)&h0; st.y = *(unsigned*)&h1;
        st.z = *(unsigned*)&h2; st.w = *(unsigned*)&h3;
        ((uint4*)g_a1h)[(size_t)w * 16 + l] = st;
    }
}

// -------- GEMM2: h2h[NN,40] = a1h[NN,128] @ W2[128,40] --------
__global__ void k_gemm2(const float* __restrict__ W2) {
    __shared__ __align__(16) float As[128][65];
    __shared__ float Bs[64][40];
    int tid = threadIdx.x;
    int r0 = blockIdx.x * 128;
    int tx = tid & 7;
    int ty = tid >> 3;
    float acc[4][5];
#pragma unroll
    for (int i = 0; i < 4; i++)
#pragma unroll
        for (int c = 0; c < 5; c++) acc[i][c] = 0.f;

    for (int kt = 0; kt < DH; kt += 64) {
#pragma unroll
        for (int q = 0; q < 8; q++) {
            int id = tid + q * 256;
            int row = id >> 4, c4 = id & 15;
            float4 v = make_float4(0.f, 0.f, 0.f, 0.f);
            if (r0 + row < NN) {
                uint2 u = *(const uint2*)(g_a1h + (size_t)(r0 + row) * DH + kt + c4 * 4);
                float2 f0 = __half22float2(*(__half2*)&u.x);
                float2 f1 = __half22float2(*(__half2*)&u.y);
                v = make_float4(f0.x, f0.y, f1.x, f1.y);
            }
            As[row][c4 * 4 + 0] = v.x; As[row][c4 * 4 + 1] = v.y;
            As[row][c4 * 4 + 2] = v.z; As[row][c4 * 4 + 3] = v.w;
        }
#pragma unroll
        for (int q = 0; q < 10; q++) {
            int id = tid + q * 256;
            int k = id / 40, c = id % 40;
            Bs[k][c] = W2[(size_t)(kt + k) * DO + c];
        }
        __syncthreads();
#pragma unroll 8
        for (int k = 0; k < 64; k++) {
            float b[5];
#pragma unroll
            for (int c = 0; c < 5; c++) b[c] = Bs[k][tx * 5 + c];
#pragma unroll
            for (int i = 0; i < 4; i++) {
                float a = As[ty * 4 + i][k];
#pragma unroll
                for (int c = 0; c < 5; c++) acc[i][c] += a * b[c];
            }
        }
        __syncthreads();
    }
#pragma unroll
    for (int i = 0; i < 4; i++) {
        int row = r0 + ty * 4 + i;
        if (row < NN) {
#pragma unroll
            for (int c = 0; c < 5; c++)
                g_h2h[(size_t)row * DO + tx * 5 + c] = __float2half_rn(acc[i][c]);
        }
    }
}

// -------- layer2 aggregation + bias + log_softmax fused, 4x unroll --------
__global__ void k_agg2_logsm(float* __restrict__ out, const float* __restrict__ B2) {
    int t = blockIdx.x * blockDim.x + threadIdx.x;
    int w = t >> 5, lane = t & 31;
    if (w >= NN) return;
    bool act = lane < 20;
    float dv = g_dinv[w];
    float c0 = dv * dv;
    const __half2* __restrict__ Hh = (const __half2*)g_h2h;
    float acc0 = 0.f, acc1 = 0.f;
    if (act) {
        float2 f = __half22float2(Hh[(size_t)w * 20 + lane]);
        acc0 = c0 * f.x;
        acc1 = c0 * f.y;
    }
    int j = g_off[w];
    int end = j + g_deg[w];
    int lidx = act ? lane : 0;
    for (; j + 4 <= end; j += 4) {
        unsigned ew[4];
#pragma unroll
        for (int q = 0; q < 4; q++) ew[q] = g_edge[j + q];
        __half2 u[4];
#pragma unroll
        for (int q = 0; q < 4; q++) u[q] = Hh[(size_t)(ew[q] >> 16) * 20 + lidx];
        if (act) {
#pragma unroll
            for (int q = 0; q < 4; q++) {
                float c = __half2float(__ushort_as_half((unsigned short)(ew[q] & 0xffffu)));
                float2 f = __half22float2(u[q]);
                acc0 += c * f.x;
                acc1 += c * f.y;
            }
        }
    }
    for (; j < end; j++) {
        unsigned e0 = g_edge[j];
        float2 f = __half22float2(Hh[(size_t)(e0 >> 16) * 20 + lidx]);
        if (act) {
            float c = __half2float(__ushort_as_half((unsigned short)(e0 & 0xffffu)));
            acc0 += c * f.x;
            acc1 += c * f.y;
        }
    }
    if (act) {
        acc0 += B2[2 * lane];
        acc1 += B2[2 * lane + 1];
    }
    float m = act ? fmaxf(acc0, acc1) : __int_as_float(0xff800000);
#pragma unroll
    for (int o = 16; o > 0; o >>= 1) m = fmaxf(m, __shfl_xor_sync(0xffffffffu, m, o));
    float s = act ? (expf(acc0 - m) + expf(acc1 - m)) : 0.f;
#pragma unroll
    for (int o = 16; o > 0; o >>= 1) s += __shfl_xor_sync(0xffffffffu, s, o);
    float lse = m + logf(s);
    if (act)
        *(float2*)(out + (size_t)w * DO + 2 * lane) = make_float2(acc0 - lse, acc1 - lse);
}

// -------- launch --------
extern "C" void kernel_launch(void* const* d_in, const int* in_sizes, int n_in,
                              void* d_out, int out_size) {
    const float* x  = (const float*)d_in[0];
    const void*  ei = d_in[1];
    const float* W1 = (const float*)d_in[2];
    const float* b1 = (const float*)d_in[3];
    const float* W2 = (const float*)d_in[4];
    const float* b2 = (const float*)d_in[5];
    float* out = (float*)d_out;

    (void)in_sizes; (void)n_in; (void)out_size;

    k_init<<<(NN + 255) / 256 + 1, 256>>>((const int*)ei);                 // 0
    k_gemm1_deg<<<GEMM1_BLOCKS + DEG_BLOCKS, 256>>>(x, W1, ei);            // 1 (overlapped)
    k_scan<<<SCAN_NB, SCAN_BLK>>>();                                       // 2
    k_scatter<<<(NE / 4 + 255) / 256, 256>>>(ei);                          // 3
    k_agg1<<<(int)(((size_t)NN * 32 + 255) / 256), 256>>>(b1);             // 4
    k_gemm2<<<(NN + 127) / 128, 256>>>(W2);                                // 5
    k_agg2_logsm<<<(int)(((size_t)NN * 32 + 255) / 256), 256>>>(out, b2);  // 6
}